// round 14
// baseline (speedup 1.0000x reference)
#include <cuda_runtime.h>
#include <cstdint>

// MedianFilterLoss, decomposed:
//   loss = sum_i softplus((1-2*t_i)*x_i)                       (base, elementwise)
//        - sum_{runs of ones, len>=3} max-weight subset of w_i = relu(-x_i)
//          with pairwise distance >= 3 (3-state max-plus DP per run)
// cp.async double-buffered persistent kernel (148 CTAs, 1/SM):
//  - prefetch tile k+1 raw x,t into skewed smem while computing tile k
//  - single fused compute pass: softplus + DP straight from raw smem
// DP reset = -0.0f; "len>=3" == sign(m0)>=0. Prefix runs: close suppressed.

#define T_LEN  16384
#define TILE   8192
#define NTH    256
#define GRID   148
#define ROWB   144                    // bytes per thread-row: 128 data + 16 pad
#define XBYTES (NTH * ROWB)           // 36864 per array
#define BUFB   (2 * XBYTES)           // x + t regions = 73728
#define NEGZ   __int_as_float(0x80000000)
#define LN2F   0.6931471805599453f

__device__ float g_partial[GRID];
__device__ unsigned int g_done;

__device__ __forceinline__ void cp16(uint32_t dst, const void* src) {
    asm volatile("cp.async.cg.shared.global [%0], [%1], 16;\n" :: "r"(dst), "l"(src));
}

extern __shared__ char dynsmem[];

__global__ void __launch_bounds__(NTH, 1) mfl_fused(const float* __restrict__ xg,
                                                    const int* __restrict__ tg,
                                                    float* __restrict__ o,
                                                    int ntiles, double inv_n) {
    __shared__ float wsum[NTH / 32];
    __shared__ double sdbl[NTH];
    __shared__ unsigned int s_last;

    const int tid  = threadIdx.x;
    const int lane = tid & 31;
    const int wid  = tid >> 5;

    uint32_t sbase;
    asm("{ .reg .u64 t0; cvta.to.shared.u64 t0, %1; cvt.u32.u64 %0, t0; }"
        : "=r"(sbase) : "l"(dynsmem));
    // per-thread cp.async dst base (k-invariant part)
    const uint32_t dstoff = (uint32_t)(tid >> 3) * ROWB + (uint32_t)(tid & 7) * 16;

    float acc  = 0.0f;     // relu terms + DP corrections
    float accL = 0.0f;     // log2 terms, * ln2 at the end

    // ---- prologue: prefetch first tile into buffer 0 ----
    int tile0 = blockIdx.x;
    if (tile0 < ntiles) {
        const char* xs = (const char*)(xg + tile0 * TILE);
        const char* ts = (const char*)(tg + tile0 * TILE);
        uint32_t dx = sbase + dstoff;
        uint32_t dt = dx + XBYTES;
#pragma unroll
        for (int k = 0; k < 8; ++k) {
            long srcoff = ((long)(tid + k * 256)) * 16;
            cp16(dx + k * 4608, xs + srcoff);
            cp16(dt + k * 4608, ts + srcoff);
        }
    }
    asm volatile("cp.async.commit_group;\n");

    int it = 0;
    for (int tile = tile0; tile < ntiles; tile += GRID, ++it) {
        const int curBuf = it & 1;
        const int nt = tile + GRID;
        // ---- prefetch next tile into the other buffer ----
        if (nt < ntiles) {
            const char* xs = (const char*)(xg + nt * TILE);
            const char* ts = (const char*)(tg + nt * TILE);
            uint32_t dx = sbase + (curBuf ^ 1) * BUFB + dstoff;
            uint32_t dt = dx + XBYTES;
#pragma unroll
            for (int k = 0; k < 8; ++k) {
                long srcoff = ((long)(tid + k * 256)) * 16;
                cp16(dx + k * 4608, xs + srcoff);
                cp16(dt + k * 4608, ts + srcoff);
            }
        }
        asm volatile("cp.async.commit_group;\n");
        asm volatile("cp.async.wait_group 1;\n");
        __syncthreads();                       // current tile data visible to all

        // ---- fused compute pass over this thread's 32 contiguous elements ----
        const int row  = tile >> 1;            // tensor row
        const int half = tile & 1;
        const int base = row * T_LEN + half * TILE;
        const float* bx = (const float*)(dynsmem + curBuf * BUFB);
        const int*   bt = (const int*)(dynsmem + curBuf * BUFB + XBYTES);
        const float* myx = bx + tid * 36;      // 36 words per row (144B)
        const int*   myt = bt + tid * 36;

        bool suppress;
        if (tid == 0) suppress = half ? (tg[base - 1] != 0) : false;
        else          suppress = (bt[(tid - 1) * 36 + 31] != 0);

        float m0 = NEGZ, m1 = NEGZ, m2 = NEGZ;
        bool b = false;
#pragma unroll
        for (int j = 0; j < 8; ++j) {
            float4 xq = reinterpret_cast<const float4*>(myx)[j];
            int4   tq = reinterpret_cast<const int4*>(myt)[j];
            float xv[4] = {xq.x, xq.y, xq.z, xq.w};
            int   tv[4] = {tq.x, tq.y, tq.z, tq.w};
#pragma unroll
            for (int e = 0; e < 4; ++e) {
                float x  = xv[e];
                b = (tv[e] != 0);
                float u  = exp2f(fabsf(x) * -1.4426950408889634f);
                accL    += __log2f(1.0f + u);
                float s  = b ? -x : x;
                float r  = fmaxf(s, 0.0f);     // relu of signed logit
                acc     += r;
                bool doclose = !b && !suppress && (__float_as_int(m0) >= 0);
                if (doclose) acc -= m2;
                suppress = suppress && b;
                float nm2 = fabsf(fmaxf(m2, m0 + r));
                m0 = b ? m1 : NEGZ;
                m1 = b ? m2 : NEGZ;
                m2 = b ? nm2 : NEGZ;
            }
        }

        // ---- suffix: open run at chunk end ----
        if (b && !suppress) {
            bool alive = true;
            if (tid < NTH - 1) {
                // 8-element overlap into next thread's row (raw smem)
                const float* nx = bx + (tid + 1) * 36;
                const int*   ntp = bt + (tid + 1) * 36;
#pragma unroll
                for (int j = 0; j < 2; ++j) {
                    float4 xq = reinterpret_cast<const float4*>(nx)[j];
                    int4   tq = reinterpret_cast<const int4*>(ntp)[j];
                    float xv[4] = {xq.x, xq.y, xq.z, xq.w};
                    int   tv[4] = {tq.x, tq.y, tq.z, tq.w};
#pragma unroll
                    for (int e = 0; e < 4; ++e) {
                        bool one = (tv[e] != 0);
                        float r = fmaxf(-xv[e], 0.0f);
                        bool cont = alive && one;
                        bool cls  = alive && !one && (__float_as_int(m0) >= 0);
                        if (cls) acc -= m2;
                        float nm2 = fabsf(fmaxf(m2, m0 + r));
                        m0 = cont ? m1 : m0;
                        m1 = cont ? m2 : m1;
                        m2 = cont ? nm2 : m2;
                        alive = cont;
                    }
                }
            }
            if (alive) {                       // rare: run alive past +8
                int p = (tid + 1) * 32 + ((tid < NTH - 1) ? 8 : 0);
                while (p < TILE) {
                    if (bt[(p >> 5) * 36 + (p & 31)] == 0) break;
                    float r = fmaxf(-bx[(p >> 5) * 36 + (p & 31)], 0.0f);
                    float nm2 = fabsf(fmaxf(m2, m0 + r));
                    m0 = m1; m1 = m2; m2 = nm2; ++p;
                }
                if (p == TILE && half == 0) {  // spill across mid-row boundary
                    int g = base + TILE;
                    const int gend = row * T_LEN + T_LEN;
                    while (g < gend && tg[g] != 0) {
                        float w = fmaxf(-xg[g], 0.0f);
                        float nm2 = fabsf(fmaxf(m2, m0 + w));
                        m0 = m1; m1 = m2; m2 = nm2; ++g;
                    }
                }
                if (__float_as_int(m0) >= 0) acc -= m2;  // close at zero / row end
            }
        }
        __syncthreads();                       // all reads done before overwrite
    }
    asm volatile("cp.async.wait_group 0;\n");

    acc = fmaf(accL, LN2F, acc);

    // ---- block reduction ----
#pragma unroll
    for (int off = 16; off; off >>= 1)
        acc += __shfl_down_sync(0xFFFFFFFFu, acc, off);
    if (lane == 0) wsum[wid] = acc;
    __syncthreads();
    float blocksum = 0.0f;
    if (wid == 0) {
        float v = (lane < NTH / 32) ? wsum[lane] : 0.0f;
#pragma unroll
        for (int off = 4; off; off >>= 1)
            v += __shfl_down_sync(0xFFFFFFFFu, v, off);
        blocksum = v;
    }

    // ---- last-block-done final reduction (single launch) ----
    if (tid == 0) {
        g_partial[blockIdx.x] = blocksum;
        __threadfence();
        unsigned old = atomicAdd(&g_done, 1u);
        s_last = (old == gridDim.x - 1) ? 1u : 0u;
    }
    __syncthreads();
    if (s_last) {
        const volatile float* gp = g_partial;
        double sv = 0.0;
        for (int i = tid; i < (int)gridDim.x; i += NTH)
            sv += (double)gp[i];
        sdbl[tid] = sv;
        __syncthreads();
#pragma unroll
        for (int off = NTH / 2; off; off >>= 1) {
            if (tid < off) sdbl[tid] += sdbl[tid + off];
            __syncthreads();
        }
        if (tid == 0) {
            o[0] = (float)(sdbl[0] * inv_n);
            g_done = 0;                        // reset for next graph replay
        }
    }
}

extern "C" void kernel_launch(void* const* d_in, const int* in_sizes, int n_in,
                              void* d_out, int out_size) {
    const float* xg = (const float*)d_in[0];
    const int*   tg = (const int*)d_in[1];
    long long n = (long long)in_sizes[0];      // 1024 * 16384
    int ntiles = (int)(n / TILE);              // 2048
    static int smem_set = 0;                   // idempotent attribute set
    if (!smem_set) {
        cudaFuncSetAttribute(mfl_fused, cudaFuncAttributeMaxDynamicSharedMemorySize,
                             2 * BUFB);
        smem_set = 1;
    }
    mfl_fused<<<GRID, NTH, 2 * BUFB>>>(xg, tg, (float*)d_out, ntiles,
                                       1.0 / (double)n);
}